// round 2
// baseline (speedup 1.0000x reference)
#include <cuda_runtime.h>
#include <cuda_bf16.h>

// Skewed L1 loss mean reduction.
// lam(y) with LIM=(0,1), MEDIAN=0.5, LMAX=1 simplifies to 2y-1 on both branches.
// term = |p - t| * exp(sign(t - p) * (2t - 1));  output = mean(term).

__global__ void zero_out_kernel(float* out) {
    out[0] = 0.0f;
}

__global__ __launch_bounds__(256) void skewed_loss_kernel(
    const float* __restrict__ y_pred,
    const float* __restrict__ y_true,
    float* __restrict__ out,
    int n4,          // number of float4 chunks
    float inv_n)
{
    const float4* p4 = reinterpret_cast<const float4*>(y_pred);
    const float4* t4 = reinterpret_cast<const float4*>(y_true);

    float acc = 0.0f;
    int stride = gridDim.x * blockDim.x;
    for (int i = blockIdx.x * blockDim.x + threadIdx.x; i < n4; i += stride) {
        float4 p = p4[i];
        float4 t = t4[i];

        {
            float d = p.x - t.x;
            float lam = 2.0f * t.x - 1.0f;
            float e = (d <= 0.0f) ? lam : -lam;
            acc += fabsf(d) * __expf(e);
        }
        {
            float d = p.y - t.y;
            float lam = 2.0f * t.y - 1.0f;
            float e = (d <= 0.0f) ? lam : -lam;
            acc += fabsf(d) * __expf(e);
        }
        {
            float d = p.z - t.z;
            float lam = 2.0f * t.z - 1.0f;
            float e = (d <= 0.0f) ? lam : -lam;
            acc += fabsf(d) * __expf(e);
        }
        {
            float d = p.w - t.w;
            float lam = 2.0f * t.w - 1.0f;
            float e = (d <= 0.0f) ? lam : -lam;
            acc += fabsf(d) * __expf(e);
        }
    }

    // Warp reduction
    #pragma unroll
    for (int off = 16; off > 0; off >>= 1)
        acc += __shfl_xor_sync(0xFFFFFFFF, acc, off);

    // Block reduction via shared
    __shared__ float warp_sums[8];
    int lane = threadIdx.x & 31;
    int wid = threadIdx.x >> 5;
    if (lane == 0) warp_sums[wid] = acc;
    __syncthreads();

    if (wid == 0) {
        float v = (lane < 8) ? warp_sums[lane] : 0.0f;
        #pragma unroll
        for (int off = 4; off > 0; off >>= 1)
            v += __shfl_xor_sync(0xFFFFFFFF, v, off);
        if (lane == 0)
            atomicAdd(out, v * inv_n);
    }
}

extern "C" void kernel_launch(void* const* d_in, const int* in_sizes, int n_in,
                              void* d_out, int out_size) {
    const float* y_pred = (const float*)d_in[0];
    const float* y_true = (const float*)d_in[1];
    float* out = (float*)d_out;

    int n = in_sizes[0];          // 33554432, divisible by 4
    int n4 = n >> 2;

    zero_out_kernel<<<1, 1>>>(out);

    const int threads = 256;
    const int blocks = 148 * 8;   // 8 blocks per SM, full-chip occupancy
    float inv_n = 1.0f / (float)n;
    skewed_loss_kernel<<<blocks, threads>>>(y_pred, y_true, out, n4, inv_n);
}